// round 2
// baseline (speedup 1.0000x reference)
#include <cuda_runtime.h>

// Problem constants (shapes are fixed by the dataset)
#define HD 128          // hidden size H
#define FN 32           // node features
#define FE 16           // edge features
#define KIN 48          // FN + FE
#define DEPTH 3
#define MAXE 500000
#define MAXN 50000

// Scratch (device globals; no allocation allowed)
__device__ float g_h0[(size_t)MAXE * HD];
__device__ float g_hA[(size_t)MAXE * HD];
__device__ float g_hB[(size_t)MAXE * HD];
__device__ float g_amsg[(size_t)MAXN * HD];

// ---------------------------------------------------------------------------
// out[g] = b_ffn  (seed the bias; pooled contributions are atomically added)
__global__ void k_init_out(float* __restrict__ out, const float* __restrict__ b_ffn, int G) {
    int t = blockIdx.x * blockDim.x + threadIdx.x;
    if (t < G) out[t] = b_ffn[0];
}

// zero a float buffer (float4 grid-stride)
__global__ void k_zero(float4* __restrict__ p, int n4) {
    int t = blockIdx.x * blockDim.x + threadIdx.x;
    for (int i = t; i < n4; i += gridDim.x * blockDim.x)
        p[i] = make_float4(0.f, 0.f, 0.f, 0.f);
}

// ---------------------------------------------------------------------------
// edge init: h0[e] = relu(cat(x[row[e]], edge_attr[e]) @ W_init + b_init)
// 128 threads = one output column each; W_init column cached in registers.
// 8 edges per block iteration.
__global__ void __launch_bounds__(128) k_edge_init(
    const float* __restrict__ x, const float* __restrict__ ea,
    const int* __restrict__ row,
    const float* __restrict__ Wi, const float* __restrict__ bi,
    float* __restrict__ h0, float* __restrict__ h, int E)
{
    __shared__ float in_sm[8][KIN];
    const int j = threadIdx.x;
    float w[KIN];
#pragma unroll
    for (int k = 0; k < KIN; k++) w[k] = Wi[k * HD + j];
    const float bj = bi[j];

    for (int e0 = blockIdx.x * 8; e0 < E; e0 += gridDim.x * 8) {
        // stage 8 edges' 48-dim inputs
        for (int idx = j; idx < 8 * KIN; idx += 128) {
            int i = idx / KIN, k = idx - i * KIN;
            int e = e0 + i;
            float v = 0.f;
            if (e < E) v = (k < FN) ? x[(size_t)row[e] * FN + k]
                                    : ea[(size_t)e * FE + (k - FN)];
            in_sm[i][k] = v;
        }
        __syncthreads();

        float acc[8];
#pragma unroll
        for (int i = 0; i < 8; i++) acc[i] = bj;
#pragma unroll
        for (int k = 0; k < KIN; k++) {
            float wv = w[k];
#pragma unroll
            for (int i = 0; i < 8; i++)
                acc[i] = fmaf(in_sm[i][k], wv, acc[i]);
        }
#pragma unroll
        for (int i = 0; i < 8; i++) {
            int e = e0 + i;
            if (e < E) {
                float r = fmaxf(acc[i], 0.f);
                h0[(size_t)e * HD + j] = r;
                h [(size_t)e * HD + j] = r;
            }
        }
        __syncthreads();
    }
}

// ---------------------------------------------------------------------------
// segment scatter: amsg[col[e]] += h[e]   (fp32 L2 atomics, float4 reads)
__global__ void __launch_bounds__(256) k_scatter(
    const float* __restrict__ h, const int* __restrict__ col,
    float* __restrict__ amsg, int E)
{
    long long idx = (long long)blockIdx.x * blockDim.x + threadIdx.x; // over E*32
    long long total = (long long)E * 32;
    if (idx >= total) return;
    int e  = (int)(idx >> 5);
    int kk = (int)(idx & 31);
    int c = col[e];
    float4 v = reinterpret_cast<const float4*>(h)[idx];
    float* dst = amsg + (size_t)c * HD + kk * 4;
    atomicAdd(dst + 0, v.x);
    atomicAdd(dst + 1, v.y);
    atomicAdd(dst + 2, v.z);
    atomicAdd(dst + 3, v.w);
}

// ---------------------------------------------------------------------------
// conv layer: hout[e] = relu((amsg[row[e]] - h[e^1]) @ W + b + h0[e])
// 128 threads = one column each; full 128-float W column in registers.
// 8 edges per block iteration, message vectors staged in smem.
__global__ void __launch_bounds__(128) k_conv(
    const float* __restrict__ amsg, const float* __restrict__ h,
    const float* __restrict__ h0,
    const float* __restrict__ W, const float* __restrict__ b,
    const int* __restrict__ row, float* __restrict__ hout, int E)
{
    __shared__ float4 msm[8][32];
    const int j = threadIdx.x;
    float w[HD];
#pragma unroll
    for (int k = 0; k < HD; k++) w[k] = W[k * HD + j];
    const float bj = b[j];

    const float4* amsg4 = reinterpret_cast<const float4*>(amsg);
    const float4* h4    = reinterpret_cast<const float4*>(h);

    for (int e0 = blockIdx.x * 8; e0 < E; e0 += gridDim.x * 8) {
        // build messages: m = amsg[row[e]] - h[pair(e)]  (two rounds of 4 edges)
#pragma unroll
        for (int rnd = 0; rnd < 2; rnd++) {
            int i = rnd * 4 + (j >> 5), kk = j & 31;
            int e = e0 + i;
            if (e < E) {
                int r = row[e];
                float4 a  = amsg4[(size_t)r * 32 + kk];
                float4 hv = h4[((size_t)(e ^ 1)) * 32 + kk];
                msm[i][kk] = make_float4(a.x - hv.x, a.y - hv.y, a.z - hv.z, a.w - hv.w);
            }
        }
        __syncthreads();

        float acc[8];
#pragma unroll
        for (int i = 0; i < 8; i++) acc[i] = bj;
#pragma unroll
        for (int kk = 0; kk < 32; kk++) {
            float w0 = w[4 * kk + 0], w1 = w[4 * kk + 1];
            float w2 = w[4 * kk + 2], w3 = w[4 * kk + 3];
#pragma unroll
            for (int i = 0; i < 8; i++) {
                float4 m = msm[i][kk];
                acc[i] = fmaf(m.x, w0, acc[i]);
                acc[i] = fmaf(m.y, w1, acc[i]);
                acc[i] = fmaf(m.z, w2, acc[i]);
                acc[i] = fmaf(m.w, w3, acc[i]);
            }
        }
#pragma unroll
        for (int i = 0; i < 8; i++) {
            int e = e0 + i;
            if (e < E)
                hout[(size_t)e * HD + j] =
                    fmaxf(acc[i] + h0[(size_t)e * HD + j], 0.f);
        }
        __syncthreads();
    }
}

// ---------------------------------------------------------------------------
// node readout: hn = relu(cat(x[n], s[n]) @ W_e2n + b_e2n);
// r = hn . W_ffn; atomicAdd(out[batch[n]], r).
// 256 threads: (j = t&127 column, half = t>>7 selects K range). 2 nodes / iter.
__global__ void __launch_bounds__(256) k_node(
    const float* __restrict__ x, const float* __restrict__ s,
    const int* __restrict__ batch,
    const float* __restrict__ We, const float* __restrict__ be,
    const float* __restrict__ wffn, float* __restrict__ out, int N)
{
    __shared__ float in_sm[2][FN + HD];     // 160 per node
    __shared__ float part[2][HD];
    __shared__ float redsm[2];
    const int t = threadIdx.x;
    const int j = t & 127;
    const int half = t >> 7;

    float w[80];
#pragma unroll
    for (int k = 0; k < 80; k++) w[k] = We[(half * 80 + k) * HD + j];
    const float bj = be[j];
    const float wf = wffn[j];

    for (int n0 = blockIdx.x * 2; n0 < N; n0 += gridDim.x * 2) {
        if (t < 2) redsm[t] = 0.f;
        // stage inputs: [x(32), s(128)] for 2 nodes
        for (int idx = t; idx < 2 * (FN + HD); idx += 256) {
            int i = idx / (FN + HD), k = idx - i * (FN + HD);
            int n = n0 + i;
            float v = 0.f;
            if (n < N) v = (k < FN) ? x[(size_t)n * FN + k]
                                    : s[(size_t)n * HD + (k - FN)];
            in_sm[i][k] = v;
        }
        __syncthreads();

        float a0 = 0.f, a1 = 0.f;
#pragma unroll
        for (int k = 0; k < 80; k++) {
            float wv = w[k];
            a0 = fmaf(in_sm[0][half * 80 + k], wv, a0);
            a1 = fmaf(in_sm[1][half * 80 + k], wv, a1);
        }
        if (half == 1) { part[0][j] = a0; part[1][j] = a1; }
        __syncthreads();

        if (half == 0) {
            float h0v = fmaxf(a0 + part[0][j] + bj, 0.f);
            float h1v = fmaxf(a1 + part[1][j] + bj, 0.f);
            float r0 = h0v * wf;
            float r1 = h1v * wf;
#pragma unroll
            for (int off = 16; off > 0; off >>= 1) {
                r0 += __shfl_down_sync(0xffffffffu, r0, off);
                r1 += __shfl_down_sync(0xffffffffu, r1, off);
            }
            if ((t & 31) == 0) {
                atomicAdd(&redsm[0], r0);
                atomicAdd(&redsm[1], r1);
            }
        }
        __syncthreads();
        if (t < 2) {
            int n = n0 + t;
            if (n < N) atomicAdd(&out[batch[n]], redsm[t]);
        }
        __syncthreads();
    }
}

// ---------------------------------------------------------------------------
extern "C" void kernel_launch(void* const* d_in, const int* in_sizes, int n_in,
                              void* d_out, int out_size)
{
    const float* x        = (const float*)d_in[0];
    const float* ea       = (const float*)d_in[1];
    const int*   eidx     = (const int*)  d_in[2];
    const int*   batch    = (const int*)  d_in[3];
    const float* W_init   = (const float*)d_in[4];
    const float* b_init   = (const float*)d_in[5];
    const float* W_convs  = (const float*)d_in[6];
    const float* b_convs  = (const float*)d_in[7];
    const float* W_e2n    = (const float*)d_in[8];
    const float* b_e2n    = (const float*)d_in[9];
    const float* W_ffn    = (const float*)d_in[10];
    const float* b_ffn    = (const float*)d_in[11];
    float* out = (float*)d_out;

    const int N = in_sizes[0] / FN;
    const int E = in_sizes[1] / FE;
    const int G = out_size;
    const int* row = eidx;
    const int* col = eidx + E;

    float* h0   = nullptr; cudaGetSymbolAddress((void**)&h0,   g_h0);
    float* hA   = nullptr; cudaGetSymbolAddress((void**)&hA,   g_hA);
    float* hB   = nullptr; cudaGetSymbolAddress((void**)&hB,   g_hB);
    float* amsg = nullptr; cudaGetSymbolAddress((void**)&amsg, g_amsg);

    k_init_out<<<1, 128>>>(out, b_ffn, G);

    const int egrid = (E + 7) / 8;
    k_edge_init<<<egrid, 128>>>(x, ea, row, W_init, b_init, h0, hA, E);

    const int amsg4 = N * HD / 4;
    const int zgrid = (amsg4 + 255) / 256;
    long long sthreads = (long long)E * 32;
    const int sgrid = (int)((sthreads + 255) / 256);

    float* hcur = hA;
    float* hnext = hB;
    for (int l = 0; l < DEPTH; l++) {
        k_zero<<<zgrid, 256>>>((float4*)amsg, amsg4);
        k_scatter<<<sgrid, 256>>>(hcur, col, amsg, E);
        k_conv<<<egrid, 128>>>(amsg, hcur, h0,
                               W_convs + (size_t)l * HD * HD,
                               b_convs + (size_t)l * HD,
                               row, hnext, E);
        float* tmp = hcur; hcur = hnext; hnext = tmp;
    }

    // final aggregation s = segment_sum(h, col)
    k_zero<<<zgrid, 256>>>((float4*)amsg, amsg4);
    k_scatter<<<sgrid, 256>>>(hcur, col, amsg, E);

    const int ngrid = (N + 1) / 2;
    k_node<<<ngrid, 256>>>(x, amsg, batch, W_e2n, b_e2n, W_ffn, out, N);
}

// round 6
// speedup vs baseline: 1.5526x; 1.5526x over previous
#include <cuda_runtime.h>
#include <cstdint>

// Problem constants
#define HD 128
#define FN 32
#define FE 16
#define KIN 48
#define DEPTH 3
#define MAXE 500000
#define MAXN 50000

// Scratch (device globals; no allocation allowed)
__device__ float g_h0[(size_t)MAXE * HD];
__device__ float g_hA[(size_t)MAXE * HD];
__device__ float g_hB[(size_t)MAXE * HD];
__device__ float g_amsg[(size_t)MAXN * HD];

// ---------------------------------------------------------------------------
__global__ void k_init_out(float* __restrict__ out, const float* __restrict__ b_ffn, int G) {
    int t = blockIdx.x * blockDim.x + threadIdx.x;
    if (t < G) out[t] = b_ffn[0];
}

__global__ void k_zero(float4* __restrict__ p, int n4) {
    int t = blockIdx.x * blockDim.x + threadIdx.x;
    for (int i = t; i < n4; i += gridDim.x * blockDim.x)
        p[i] = make_float4(0.f, 0.f, 0.f, 0.f);
}

// ---------------------------------------------------------------------------
// edge init: h0[e] = relu(cat(x[row[e]], edge_attr[e]) @ W_init + b_init)
__global__ void __launch_bounds__(128) k_edge_init(
    const float* __restrict__ x, const float* __restrict__ ea,
    const int* __restrict__ row,
    const float* __restrict__ Wi, const float* __restrict__ bi,
    float* __restrict__ h0, float* __restrict__ h, int E)
{
    __shared__ float in_sm[8][KIN];
    const int j = threadIdx.x;
    float w[KIN];
#pragma unroll
    for (int k = 0; k < KIN; k++) w[k] = Wi[k * HD + j];
    const float bj = bi[j];

    for (int e0 = blockIdx.x * 8; e0 < E; e0 += gridDim.x * 8) {
        for (int idx = j; idx < 8 * KIN; idx += 128) {
            int i = idx / KIN, k = idx - i * KIN;
            int e = e0 + i;
            float v = 0.f;
            if (e < E) v = (k < FN) ? x[(size_t)row[e] * FN + k]
                                    : ea[(size_t)e * FE + (k - FN)];
            in_sm[i][k] = v;
        }
        __syncthreads();

        float acc[8];
#pragma unroll
        for (int i = 0; i < 8; i++) acc[i] = bj;
#pragma unroll
        for (int k = 0; k < KIN; k++) {
            float wv = w[k];
#pragma unroll
            for (int i = 0; i < 8; i++)
                acc[i] = fmaf(in_sm[i][k], wv, acc[i]);
        }
#pragma unroll
        for (int i = 0; i < 8; i++) {
            int e = e0 + i;
            if (e < E) {
                float r = fmaxf(acc[i], 0.f);
                h0[(size_t)e * HD + j] = r;
                h [(size_t)e * HD + j] = r;
            }
        }
        __syncthreads();
    }
}

// ---------------------------------------------------------------------------
// segment scatter: amsg[col[e]] += h[e]   (fp32 L2 atomics, float4 reads)
__global__ void __launch_bounds__(256) k_scatter(
    const float* __restrict__ h, const int* __restrict__ col,
    float* __restrict__ amsg, int E)
{
    long long idx = (long long)blockIdx.x * blockDim.x + threadIdx.x;
    long long total = (long long)E * 32;
    if (idx >= total) return;
    int e  = (int)(idx >> 5);
    int kk = (int)(idx & 31);
    int c = col[e];
    float4 v = reinterpret_cast<const float4*>(h)[idx];
    float* dst = amsg + (size_t)c * HD + kk * 4;
    atomicAdd(dst + 0, v.x);
    atomicAdd(dst + 1, v.y);
    atomicAdd(dst + 2, v.z);
    atomicAdd(dst + 3, v.w);
}

// ---------------------------------------------------------------------------
// conv layer via 3xTF32 mma.sync (error-compensated tensor-core GEMM).
// hout[e] = relu((amsg[row[e]] - h[e^1]) @ W + b + h0[e])
// One 128x128 output tile per CTA; K=128 in two 64-chunks.
// smem (floats): Ahi[128][68], Alo[128][68], Bhi[64][136], Blo[64][136], bias[128]
#define A2_STRIDE 68
#define B2_STRIDE 136
#define OFF_AHI 0
#define OFF_ALO (128 * A2_STRIDE)
#define OFF_BHI (2 * 128 * A2_STRIDE)
#define OFF_BLO (2 * 128 * A2_STRIDE + 64 * B2_STRIDE)
#define OFF_BIAS (2 * 128 * A2_STRIDE + 2 * 64 * B2_STRIDE)
#define MSM_TOTAL ((OFF_BIAS + 128) * 4)

__device__ __forceinline__ void mma_tf32(float& c0, float& c1, float& c2, float& c3,
                                         uint32_t a0, uint32_t a1, uint32_t a2, uint32_t a3,
                                         uint32_t b0, uint32_t b1) {
    asm volatile("mma.sync.aligned.m16n8k8.row.col.f32.tf32.tf32.f32 "
                 "{%0,%1,%2,%3}, {%4,%5,%6,%7}, {%8,%9}, {%0,%1,%2,%3};"
                 : "+f"(c0), "+f"(c1), "+f"(c2), "+f"(c3)
                 : "r"(a0), "r"(a1), "r"(a2), "r"(a3), "r"(b0), "r"(b1));
}

__device__ __forceinline__ void split_tf32(float v, float& hi, float& lo) {
    hi = __uint_as_float(__float_as_uint(v) & 0xFFFFE000u);
    lo = v - hi;
}

__global__ void __launch_bounds__(256, 1) k_conv_mma(
    const float* __restrict__ amsg, const float* __restrict__ h,
    const float* __restrict__ h0,
    const float* __restrict__ W, const float* __restrict__ b,
    const int* __restrict__ row, float* __restrict__ hout, int E)
{
    extern __shared__ float smf[];
    float* Ahi = smf + OFF_AHI;
    float* Alo = smf + OFF_ALO;
    float* Bhi = smf + OFF_BHI;
    float* Blo = smf + OFF_BLO;
    float* bsm = smf + OFF_BIAS;

    const int tid = threadIdx.x;
    const int wid = tid >> 5;
    const int lid = tid & 31;

    if (tid < 128) bsm[tid] = b[tid];

    const int e0 = blockIdx.x << 7;
    const float4* amsg4 = reinterpret_cast<const float4*>(amsg);
    const float4* h4    = reinterpret_cast<const float4*>(h);

    // per-thread gather bases (2 threads per edge row)
    const int r2 = tid >> 1;
    const int half = tid & 1;
    const int e_g = e0 + r2;
    const bool gvalid = (e_g < E);
    const float4* ap = nullptr;
    const float4* hp = nullptr;
    if (gvalid) {
        ap = amsg4 + (size_t)row[e_g] * 32 + half * 8;
        hp = h4 + (size_t)(e_g ^ 1) * 32 + half * 8;
    }

    // mma lane mapping
    const int m0 = wid * 16;
    const int qr = lid >> 2;        // 0..7
    const int qc = lid & 3;         // 0..3
    float acc[16][4];
#pragma unroll
    for (int nb = 0; nb < 16; nb++)
#pragma unroll
        for (int q = 0; q < 4; q++) acc[nb][q] = 0.f;

    const float* ahi_lo = &Ahi[(m0 + qr) * A2_STRIDE + qc];
    const float* ahi_hi = &Ahi[(m0 + qr + 8) * A2_STRIDE + qc];
    const float* alo_lo = &Alo[(m0 + qr) * A2_STRIDE + qc];
    const float* alo_hi = &Alo[(m0 + qr + 8) * A2_STRIDE + qc];
    const float* bhi_p  = &Bhi[qc * B2_STRIDE + qr];
    const float* blo_p  = &Blo[qc * B2_STRIDE + qr];

#pragma unroll
    for (int kc = 0; kc < 2; kc++) {
        // ---- stage A chunk: 64 k-values per row, hi/lo split
        if (gvalid) {
            float* arh = &Ahi[r2 * A2_STRIDE + half * 32];
            float* arl = &Alo[r2 * A2_STRIDE + half * 32];
            const float4* apc = ap + kc * 16;
            const float4* hpc = hp + kc * 16;
#pragma unroll
            for (int q = 0; q < 8; q++) {
                float4 a = apc[q];
                float4 hv = hpc[q];
                float m[4] = {a.x - hv.x, a.y - hv.y, a.z - hv.z, a.w - hv.w};
                float hi[4], lo[4];
#pragma unroll
                for (int u = 0; u < 4; u++) split_tf32(m[u], hi[u], lo[u]);
                *reinterpret_cast<float4*>(&arh[q * 4]) = make_float4(hi[0], hi[1], hi[2], hi[3]);
                *reinterpret_cast<float4*>(&arl[q * 4]) = make_float4(lo[0], lo[1], lo[2], lo[3]);
            }
        }
        // ---- stage B chunk: W rows [kc*64, kc*64+64), hi/lo split
        {
            const float4* W4 = reinterpret_cast<const float4*>(W) + kc * 64 * 32;
            for (int idx = tid; idx < 64 * 32; idx += 256) {
                int k = idx >> 5, n4 = idx & 31;
                float4 wv = W4[idx];
                float hi[4], lo[4];
                split_tf32(wv.x, hi[0], lo[0]);
                split_tf32(wv.y, hi[1], lo[1]);
                split_tf32(wv.z, hi[2], lo[2]);
                split_tf32(wv.w, hi[3], lo[3]);
                *reinterpret_cast<float4*>(&Bhi[k * B2_STRIDE + n4 * 4]) = make_float4(hi[0], hi[1], hi[2], hi[3]);
                *reinterpret_cast<float4*>(&Blo[k * B2_STRIDE + n4 * 4]) = make_float4(lo[0], lo[1], lo[2], lo[3]);
            }
        }
        __syncthreads();

        // ---- MMA over this 64-K chunk
#pragma unroll
        for (int ks = 0; ks < 8; ks++) {
            const int k0 = ks * 8;
            uint32_t ah0 = __float_as_uint(ahi_lo[k0]);
            uint32_t ah1 = __float_as_uint(ahi_hi[k0]);
            uint32_t ah2 = __float_as_uint(ahi_lo[k0 + 4]);
            uint32_t ah3 = __float_as_uint(ahi_hi[k0 + 4]);
            uint32_t al0 = __float_as_uint(alo_lo[k0]);
            uint32_t al1 = __float_as_uint(alo_hi[k0]);
            uint32_t al2 = __float_as_uint(alo_lo[k0 + 4]);
            uint32_t al3 = __float_as_uint(alo_hi[k0 + 4]);
            const float* bhk = bhi_p + k0 * B2_STRIDE;
            const float* blk = blo_p + k0 * B2_STRIDE;
#pragma unroll
            for (int nb = 0; nb < 16; nb++) {
                uint32_t bh0 = __float_as_uint(bhk[nb * 8]);
                uint32_t bh1 = __float_as_uint(bhk[4 * B2_STRIDE + nb * 8]);
                uint32_t bl0 = __float_as_uint(blk[nb * 8]);
                uint32_t bl1 = __float_as_uint(blk[4 * B2_STRIDE + nb * 8]);
                // lo terms first, hi*hi last
                mma_tf32(acc[nb][0], acc[nb][1], acc[nb][2], acc[nb][3],
                         al0, al1, al2, al3, bh0, bh1);
                mma_tf32(acc[nb][0], acc[nb][1], acc[nb][2], acc[nb][3],
                         ah0, ah1, ah2, ah3, bl0, bl1);
                mma_tf32(acc[nb][0], acc[nb][1], acc[nb][2], acc[nb][3],
                         ah0, ah1, ah2, ah3, bh0, bh1);
            }
        }
        __syncthreads();
    }

    // epilogue: c0,c1 -> row m0+qr cols (qc*2, qc*2+1); c2,c3 -> row m0+qr+8
    {
        const int ccol = qc * 2;
#pragma unroll
        for (int hrow = 0; hrow < 2; hrow++) {
            const int e = e0 + m0 + qr + hrow * 8;
            if (e < E) {
                const float* h0p = h0 + (size_t)e * HD;
                float* op = hout + (size_t)e * HD;
#pragma unroll
                for (int nb = 0; nb < 16; nb++) {
                    const int col = nb * 8 + ccol;
                    float2 hz = *reinterpret_cast<const float2*>(&h0p[col]);
                    float v0 = acc[nb][hrow * 2 + 0] + bsm[col]     + hz.x;
                    float v1 = acc[nb][hrow * 2 + 1] + bsm[col + 1] + hz.y;
                    float2 o = make_float2(fmaxf(v0, 0.f), fmaxf(v1, 0.f));
                    *reinterpret_cast<float2*>(&op[col]) = o;
                }
            }
        }
    }
}

// ---------------------------------------------------------------------------
// node readout (unchanged)
__global__ void __launch_bounds__(256) k_node(
    const float* __restrict__ x, const float* __restrict__ s,
    const int* __restrict__ batch,
    const float* __restrict__ We, const float* __restrict__ be,
    const float* __restrict__ wffn, float* __restrict__ out, int N)
{
    __shared__ float in_sm[2][FN + HD];
    __shared__ float part[2][HD];
    __shared__ float redsm[2];
    const int t = threadIdx.x;
    const int j = t & 127;
    const int half = t >> 7;

    float w[80];
#pragma unroll
    for (int k = 0; k < 80; k++) w[k] = We[(half * 80 + k) * HD + j];
    const float bj = be[j];
    const float wf = wffn[j];

    for (int n0 = blockIdx.x * 2; n0 < N; n0 += gridDim.x * 2) {
        if (t < 2) redsm[t] = 0.f;
        for (int idx = t; idx < 2 * (FN + HD); idx += 256) {
            int i = idx / (FN + HD), k = idx - i * (FN + HD);
            int n = n0 + i;
            float v = 0.f;
            if (n < N) v = (k < FN) ? x[(size_t)n * FN + k]
                                    : s[(size_t)n * HD + (k - FN)];
            in_sm[i][k] = v;
        }
        __syncthreads();

        float a0 = 0.f, a1 = 0.f;
#pragma unroll
        for (int k = 0; k < 80; k++) {
            float wv = w[k];
            a0 = fmaf(in_sm[0][half * 80 + k], wv, a0);
            a1 = fmaf(in_sm[1][half * 80 + k], wv, a1);
        }
        if (half == 1) { part[0][j] = a0; part[1][j] = a1; }
        __syncthreads();

        if (half == 0) {
            float h0v = fmaxf(a0 + part[0][j] + bj, 0.f);
            float h1v = fmaxf(a1 + part[1][j] + bj, 0.f);
            float r0 = h0v * wf;
            float r1 = h1v * wf;
#pragma unroll
            for (int off = 16; off > 0; off >>= 1) {
                r0 += __shfl_down_sync(0xffffffffu, r0, off);
                r1 += __shfl_down_sync(0xffffffffu, r1, off);
            }
            if ((t & 31) == 0) {
                atomicAdd(&redsm[0], r0);
                atomicAdd(&redsm[1], r1);
            }
        }
        __syncthreads();
        if (t < 2) {
            int n = n0 + t;
            if (n < N) atomicAdd(&out[batch[n]], redsm[t]);
        }
        __syncthreads();
    }
}

// ---------------------------------------------------------------------------
extern "C" void kernel_launch(void* const* d_in, const int* in_sizes, int n_in,
                              void* d_out, int out_size)
{
    const float* x        = (const float*)d_in[0];
    const float* ea       = (const float*)d_in[1];
    const int*   eidx     = (const int*)  d_in[2];
    const int*   batch    = (const int*)  d_in[3];
    const float* W_init   = (const float*)d_in[4];
    const float* b_init   = (const float*)d_in[5];
    const float* W_convs  = (const float*)d_in[6];
    const float* b_convs  = (const float*)d_in[7];
    const float* W_e2n    = (const float*)d_in[8];
    const float* b_e2n    = (const float*)d_in[9];
    const float* W_ffn    = (const float*)d_in[10];
    const float* b_ffn    = (const float*)d_in[11];
    float* out = (float*)d_out;

    const int N = in_sizes[0] / FN;
    const int E = in_sizes[1] / FE;
    const int G = out_size;
    const int* row = eidx;
    const int* col = eidx + E;

    float* h0   = nullptr; cudaGetSymbolAddress((void**)&h0,   g_h0);
    float* hA   = nullptr; cudaGetSymbolAddress((void**)&hA,   g_hA);
    float* hB   = nullptr; cudaGetSymbolAddress((void**)&hB,   g_hB);
    float* amsg = nullptr; cudaGetSymbolAddress((void**)&amsg, g_amsg);

    cudaFuncSetAttribute(k_conv_mma, cudaFuncAttributeMaxDynamicSharedMemorySize, MSM_TOTAL);

    k_init_out<<<1, 128>>>(out, b_ffn, G);

    const int egrid = (E + 7) / 8;
    k_edge_init<<<egrid, 128>>>(x, ea, row, W_init, b_init, h0, hA, E);

    const int amsg4 = N * HD / 4;
    const int zgrid = (amsg4 + 255) / 256;
    long long sthreads = (long long)E * 32;
    const int sgrid = (int)((sthreads + 255) / 256);
    const int ntiles = (E + 127) / 128;

    float* hcur = hA;
    float* hnext = hB;
    for (int l = 0; l < DEPTH; l++) {
        k_zero<<<zgrid, 256>>>((float4*)amsg, amsg4);
        k_scatter<<<sgrid, 256>>>(hcur, col, amsg, E);
        k_conv_mma<<<ntiles, 256, MSM_TOTAL>>>(amsg, hcur, h0,
                               W_convs + (size_t)l * HD * HD,
                               b_convs + (size_t)l * HD,
                               row, hnext, E);
        float* tmp = hcur; hcur = hnext; hnext = tmp;
    }

    k_zero<<<zgrid, 256>>>((float4*)amsg, amsg4);
    k_scatter<<<sgrid, 256>>>(hcur, col, amsg, E);

    const int ngrid = (N + 1) / 2;
    k_node<<<ngrid, 256>>>(x, amsg, batch, W_e2n, b_e2n, W_ffn, out, N);
}

// round 7
// speedup vs baseline: 1.7296x; 1.1140x over previous
#include <cuda_runtime.h>
#include <cstdint>

// Problem constants
#define HD 128
#define FN 32
#define FE 16
#define KIN 48
#define DEPTH 3
#define MAXE 500000
#define MAXN 50000

// Scratch (device globals; no allocation allowed)
__device__ float g_h0[(size_t)MAXE * HD];
__device__ float g_hA[(size_t)MAXE * HD];
__device__ float g_hB[(size_t)MAXE * HD];
__device__ float g_amsg[(size_t)MAXN * HD];

// ---------------------------------------------------------------------------
__global__ void k_init_out(float* __restrict__ out, const float* __restrict__ b_ffn, int G) {
    int t = blockIdx.x * blockDim.x + threadIdx.x;
    if (t < G) out[t] = b_ffn[0];
}

__global__ void k_zero(float4* __restrict__ p, int n4) {
    int t = blockIdx.x * blockDim.x + threadIdx.x;
    for (int i = t; i < n4; i += gridDim.x * blockDim.x)
        p[i] = make_float4(0.f, 0.f, 0.f, 0.f);
}

// ---------------------------------------------------------------------------
// edge init: h0[e] = relu(cat(x[row[e]], edge_attr[e]) @ W_init + b_init)
__global__ void __launch_bounds__(128) k_edge_init(
    const float* __restrict__ x, const float* __restrict__ ea,
    const int* __restrict__ row,
    const float* __restrict__ Wi, const float* __restrict__ bi,
    float* __restrict__ h0, float* __restrict__ h, int E)
{
    __shared__ float in_sm[8][KIN];
    const int j = threadIdx.x;
    float w[KIN];
#pragma unroll
    for (int k = 0; k < KIN; k++) w[k] = Wi[k * HD + j];
    const float bj = bi[j];

    for (int e0 = blockIdx.x * 8; e0 < E; e0 += gridDim.x * 8) {
        for (int idx = j; idx < 8 * KIN; idx += 128) {
            int i = idx / KIN, k = idx - i * KIN;
            int e = e0 + i;
            float v = 0.f;
            if (e < E) v = (k < FN) ? x[(size_t)row[e] * FN + k]
                                    : ea[(size_t)e * FE + (k - FN)];
            in_sm[i][k] = v;
        }
        __syncthreads();

        float acc[8];
#pragma unroll
        for (int i = 0; i < 8; i++) acc[i] = bj;
#pragma unroll
        for (int k = 0; k < KIN; k++) {
            float wv = w[k];
#pragma unroll
            for (int i = 0; i < 8; i++)
                acc[i] = fmaf(in_sm[i][k], wv, acc[i]);
        }
#pragma unroll
        for (int i = 0; i < 8; i++) {
            int e = e0 + i;
            if (e < E) {
                float r = fmaxf(acc[i], 0.f);
                h0[(size_t)e * HD + j] = r;
                h [(size_t)e * HD + j] = r;
            }
        }
        __syncthreads();
    }
}

// ---------------------------------------------------------------------------
// segment scatter: amsg[col[e]] += h[e]   (fp32 L2 atomics, float4 reads)
__global__ void __launch_bounds__(256) k_scatter(
    const float* __restrict__ h, const int* __restrict__ col,
    float* __restrict__ amsg, int E)
{
    long long idx = (long long)blockIdx.x * blockDim.x + threadIdx.x;
    long long total = (long long)E * 32;
    if (idx >= total) return;
    int e  = (int)(idx >> 5);
    int kk = (int)(idx & 31);
    int c = col[e];
    float4 v = reinterpret_cast<const float4*>(h)[idx];
    float* dst = amsg + (size_t)c * HD + kk * 4;
    atomicAdd(dst + 0, v.x);
    atomicAdd(dst + 1, v.y);
    atomicAdd(dst + 2, v.z);
    atomicAdd(dst + 3, v.w);
}

// ---------------------------------------------------------------------------
// conv layer via 3xTF32 mma.sync; fp32 operands in smem, hi/lo split in regs.
// hout[e] = relu((amsg[row[e]] - h[e^1]) @ W + b + h0[e])
// One 128x128 output tile per CTA; K=128 in two 64-chunks. 2 CTAs/SM.
// smem (floats): A[128][68], B[64][136], bias[128]  -> 70,144 B
#define A2_STRIDE 68
#define B2_STRIDE 136
#define OFF_A 0
#define OFF_B (128 * A2_STRIDE)
#define OFF_BIAS (128 * A2_STRIDE + 64 * B2_STRIDE)
#define MSM_TOTAL ((OFF_BIAS + 128) * 4)

__device__ __forceinline__ void mma_tf32(float& c0, float& c1, float& c2, float& c3,
                                         uint32_t a0, uint32_t a1, uint32_t a2, uint32_t a3,
                                         uint32_t b0, uint32_t b1) {
    asm volatile("mma.sync.aligned.m16n8k8.row.col.f32.tf32.tf32.f32 "
                 "{%0,%1,%2,%3}, {%4,%5,%6,%7}, {%8,%9}, {%0,%1,%2,%3};"
                 : "+f"(c0), "+f"(c1), "+f"(c2), "+f"(c3)
                 : "r"(a0), "r"(a1), "r"(a2), "r"(a3), "r"(b0), "r"(b1));
}

__device__ __forceinline__ void split_tf32(float v, uint32_t& hi, uint32_t& lo) {
    uint32_t h = __float_as_uint(v) & 0xFFFFE000u;
    hi = h;
    lo = __float_as_uint(v - __uint_as_float(h));
}

__global__ void __launch_bounds__(256, 2) k_conv_mma(
    const float* __restrict__ amsg, const float* __restrict__ h,
    const float* __restrict__ h0,
    const float* __restrict__ W, const float* __restrict__ b,
    const int* __restrict__ row, float* __restrict__ hout, int E)
{
    extern __shared__ float smf[];
    float* Asm = smf + OFF_A;
    float* Bsm = smf + OFF_B;
    float* bsm = smf + OFF_BIAS;

    const int tid = threadIdx.x;
    const int wid = tid >> 5;
    const int lid = tid & 31;

    if (tid < 128) bsm[tid] = b[tid];

    const int e0 = blockIdx.x << 7;
    const float4* amsg4 = reinterpret_cast<const float4*>(amsg);
    const float4* h4    = reinterpret_cast<const float4*>(h);

    // per-thread gather bases (2 threads per edge row)
    const int r2 = tid >> 1;
    const int half = tid & 1;
    const int e_g = e0 + r2;
    const bool gvalid = (e_g < E);
    const float4* ap = nullptr;
    const float4* hp = nullptr;
    if (gvalid) {
        ap = amsg4 + (size_t)row[e_g] * 32 + half * 8;
        hp = h4 + (size_t)(e_g ^ 1) * 32 + half * 8;
    }

    // mma lane mapping
    const int m0 = wid * 16;
    const int qr = lid >> 2;        // 0..7
    const int qc = lid & 3;         // 0..3
    float acc[16][4];
#pragma unroll
    for (int nb = 0; nb < 16; nb++)
#pragma unroll
        for (int q = 0; q < 4; q++) acc[nb][q] = 0.f;

    const float* a_lo_p = &Asm[(m0 + qr) * A2_STRIDE + qc];
    const float* a_hi_p = &Asm[(m0 + qr + 8) * A2_STRIDE + qc];
    const float* b_p    = &Bsm[qc * B2_STRIDE + qr];

#pragma unroll
    for (int kc = 0; kc < 2; kc++) {
        // ---- stage A chunk (fp32): 64 k-values per row
        if (gvalid) {
            float* arow = &Asm[r2 * A2_STRIDE + half * 32];
            const float4* apc = ap + kc * 16;
            const float4* hpc = hp + kc * 16;
#pragma unroll
            for (int q = 0; q < 8; q++) {
                float4 a = apc[q];
                float4 hv = hpc[q];
                *reinterpret_cast<float4*>(&arow[q * 4]) =
                    make_float4(a.x - hv.x, a.y - hv.y, a.z - hv.z, a.w - hv.w);
            }
        }
        // ---- stage B chunk (fp32): W rows [kc*64, kc*64+64)
        {
            const float4* W4 = reinterpret_cast<const float4*>(W) + kc * 64 * 32;
            for (int idx = tid; idx < 64 * 32; idx += 256) {
                int k = idx >> 5, n4 = idx & 31;
                *reinterpret_cast<float4*>(&Bsm[k * B2_STRIDE + n4 * 4]) = W4[idx];
            }
        }
        __syncthreads();

        // ---- MMA over this 64-K chunk (split in registers)
#pragma unroll
        for (int ks = 0; ks < 8; ks++) {
            const int k0 = ks * 8;
            uint32_t ah0, al0, ah1, al1, ah2, al2, ah3, al3;
            split_tf32(a_lo_p[k0],     ah0, al0);
            split_tf32(a_hi_p[k0],     ah1, al1);
            split_tf32(a_lo_p[k0 + 4], ah2, al2);
            split_tf32(a_hi_p[k0 + 4], ah3, al3);
            const float* bk = b_p + k0 * B2_STRIDE;
#pragma unroll
            for (int nb = 0; nb < 16; nb++) {
                uint32_t bh0, bl0, bh1, bl1;
                split_tf32(bk[nb * 8],                  bh0, bl0);
                split_tf32(bk[4 * B2_STRIDE + nb * 8],  bh1, bl1);
                // lo terms first, hi*hi last
                mma_tf32(acc[nb][0], acc[nb][1], acc[nb][2], acc[nb][3],
                         al0, al1, al2, al3, bh0, bh1);
                mma_tf32(acc[nb][0], acc[nb][1], acc[nb][2], acc[nb][3],
                         ah0, ah1, ah2, ah3, bl0, bl1);
                mma_tf32(acc[nb][0], acc[nb][1], acc[nb][2], acc[nb][3],
                         ah0, ah1, ah2, ah3, bh0, bh1);
            }
        }
        __syncthreads();
    }

    // epilogue: c0,c1 -> row m0+qr cols (qc*2, qc*2+1); c2,c3 -> row m0+qr+8
    {
        const int ccol = qc * 2;
#pragma unroll
        for (int hrow = 0; hrow < 2; hrow++) {
            const int e = e0 + m0 + qr + hrow * 8;
            if (e < E) {
                const float* h0p = h0 + (size_t)e * HD;
                float* op = hout + (size_t)e * HD;
#pragma unroll
                for (int nb = 0; nb < 16; nb++) {
                    const int col = nb * 8 + ccol;
                    float2 hz = *reinterpret_cast<const float2*>(&h0p[col]);
                    float v0 = acc[nb][hrow * 2 + 0] + bsm[col]     + hz.x;
                    float v1 = acc[nb][hrow * 2 + 1] + bsm[col + 1] + hz.y;
                    float2 o = make_float2(fmaxf(v0, 0.f), fmaxf(v1, 0.f));
                    *reinterpret_cast<float2*>(&op[col]) = o;
                }
            }
        }
    }
}

// ---------------------------------------------------------------------------
// node readout (unchanged)
__global__ void __launch_bounds__(256) k_node(
    const float* __restrict__ x, const float* __restrict__ s,
    const int* __restrict__ batch,
    const float* __restrict__ We, const float* __restrict__ be,
    const float* __restrict__ wffn, float* __restrict__ out, int N)
{
    __shared__ float in_sm[2][FN + HD];
    __shared__ float part[2][HD];
    __shared__ float redsm[2];
    const int t = threadIdx.x;
    const int j = t & 127;
    const int half = t >> 7;

    float w[80];
#pragma unroll
    for (int k = 0; k < 80; k++) w[k] = We[(half * 80 + k) * HD + j];
    const float bj = be[j];
    const float wf = wffn[j];

    for (int n0 = blockIdx.x * 2; n0 < N; n0 += gridDim.x * 2) {
        if (t < 2) redsm[t] = 0.f;
        for (int idx = t; idx < 2 * (FN + HD); idx += 256) {
            int i = idx / (FN + HD), k = idx - i * (FN + HD);
            int n = n0 + i;
            float v = 0.f;
            if (n < N) v = (k < FN) ? x[(size_t)n * FN + k]
                                    : s[(size_t)n * HD + (k - FN)];
            in_sm[i][k] = v;
        }
        __syncthreads();

        float a0 = 0.f, a1 = 0.f;
#pragma unroll
        for (int k = 0; k < 80; k++) {
            float wv = w[k];
            a0 = fmaf(in_sm[0][half * 80 + k], wv, a0);
            a1 = fmaf(in_sm[1][half * 80 + k], wv, a1);
        }
        if (half == 1) { part[0][j] = a0; part[1][j] = a1; }
        __syncthreads();

        if (half == 0) {
            float h0v = fmaxf(a0 + part[0][j] + bj, 0.f);
            float h1v = fmaxf(a1 + part[1][j] + bj, 0.f);
            float r0 = h0v * wf;
            float r1 = h1v * wf;
#pragma unroll
            for (int off = 16; off > 0; off >>= 1) {
                r0 += __shfl_down_sync(0xffffffffu, r0, off);
                r1 += __shfl_down_sync(0xffffffffu, r1, off);
            }
            if ((t & 31) == 0) {
                atomicAdd(&redsm[0], r0);
                atomicAdd(&redsm[1], r1);
            }
        }
        __syncthreads();
        if (t < 2) {
            int n = n0 + t;
            if (n < N) atomicAdd(&out[batch[n]], redsm[t]);
        }
        __syncthreads();
    }
}

// ---------------------------------------------------------------------------
extern "C" void kernel_launch(void* const* d_in, const int* in_sizes, int n_in,
                              void* d_out, int out_size)
{
    const float* x        = (const float*)d_in[0];
    const float* ea       = (const float*)d_in[1];
    const int*   eidx     = (const int*)  d_in[2];
    const int*   batch    = (const int*)  d_in[3];
    const float* W_init   = (const float*)d_in[4];
    const float* b_init   = (const float*)d_in[5];
    const float* W_convs  = (const float*)d_in[6];
    const float* b_convs  = (const float*)d_in[7];
    const float* W_e2n    = (const float*)d_in[8];
    const float* b_e2n    = (const float*)d_in[9];
    const float* W_ffn    = (const float*)d_in[10];
    const float* b_ffn    = (const float*)d_in[11];
    float* out = (float*)d_out;

    const int N = in_sizes[0] / FN;
    const int E = in_sizes[1] / FE;
    const int G = out_size;
    const int* row = eidx;
    const int* col = eidx + E;

    float* h0   = nullptr; cudaGetSymbolAddress((void**)&h0,   g_h0);
    float* hA   = nullptr; cudaGetSymbolAddress((void**)&hA,   g_hA);
    float* hB   = nullptr; cudaGetSymbolAddress((void**)&hB,   g_hB);
    float* amsg = nullptr; cudaGetSymbolAddress((void**)&amsg, g_amsg);

    cudaFuncSetAttribute(k_conv_mma, cudaFuncAttributeMaxDynamicSharedMemorySize, MSM_TOTAL);

    k_init_out<<<1, 128>>>(out, b_ffn, G);

    const int egrid = (E + 7) / 8;
    k_edge_init<<<egrid, 128>>>(x, ea, row, W_init, b_init, h0, hA, E);

    const int amsg4 = N * HD / 4;
    const int zgrid = (amsg4 + 255) / 256;
    long long sthreads = (long long)E * 32;
    const int sgrid = (int)((sthreads + 255) / 256);
    const int ntiles = (E + 127) / 128;

    float* hcur = hA;
    float* hnext = hB;
    for (int l = 0; l < DEPTH; l++) {
        k_zero<<<zgrid, 256>>>((float4*)amsg, amsg4);
        k_scatter<<<sgrid, 256>>>(hcur, col, amsg, E);
        k_conv_mma<<<ntiles, 256, MSM_TOTAL>>>(amsg, hcur, h0,
                               W_convs + (size_t)l * HD * HD,
                               b_convs + (size_t)l * HD,
                               row, hnext, E);
        float* tmp = hcur; hcur = hnext; hnext = tmp;
    }

    k_zero<<<zgrid, 256>>>((float4*)amsg, amsg4);
    k_scatter<<<sgrid, 256>>>(hcur, col, amsg, E);

    const int ngrid = (N + 1) / 2;
    k_node<<<ngrid, 256>>>(x, amsg, batch, W_e2n, b_e2n, W_ffn, out, N);
}